// round 4
// baseline (speedup 1.0000x reference)
#include <cuda_runtime.h>
#include <cstdint>
#include <cstddef>

// Problem dims
#define BDIM 4096
#define KDIM 1024
#define HDIM 1024
#define NDIM 6144           // 6 gates * H

// GEMM tiling: CTA 128x128, 4 warps of 64x64, 2 CTAs/SM
#define BM 128
#define BN 128
#define BK 32
#define SS 40               // smem row stride in floats (160B: 16B-aligned, LDS.64 conflict-free)
#define TILE_FLOATS (128 * SS)

// Scratch: Z[B,6H] (gate-4 slot holds wx4), U4[B,H] holds uh4
__device__ float g_Z[(size_t)BDIM * NDIM];
__device__ float g_U4[(size_t)BDIM * HDIM];

__device__ __forceinline__ void cp_async16(void* smem_ptr, const void* gmem_ptr) {
    uint32_t s = (uint32_t)__cvta_generic_to_shared(smem_ptr);
    asm volatile("cp.async.cg.shared.global [%0], [%1], 16;\n" :: "r"(s), "l"(gmem_ptr));
}

// One fused GEMM: Z = x*W^T + h*U^T (joint K=2048) for all gates; gate-4 tiles
// flush wx4 at the K midpoint and restart accumulation for uh4 -> U4.
__global__ __launch_bounds__(128, 2)
void xlstm_gemm_kernel(const float* __restrict__ xin, const float* __restrict__ hin,
                       const float* __restrict__ W,   const float* __restrict__ U,
                       float* __restrict__ Z, float* __restrict__ U4) {
    extern __shared__ float smem[];
    // layout: As[2][TILE_FLOATS], Bs[2][TILE_FLOATS]

    const int tid  = threadIdx.x;
    const int warp = tid >> 5;
    const int lane = tid & 31;
    const int wm = warp >> 1;       // 2 warps along M (64 rows each)
    const int wn = warp & 1;        // 2 warps along N (64 cols each)
    const int g  = lane >> 2;       // 0..7
    const int tg = lane & 3;        // 0..3

    const int bm = blockIdx.y * BM;
    const int bn = blockIdx.x * BN;
    const bool g4 = (blockIdx.x >= 32) && (blockIdx.x < 40);   // cols [4096,5120)

    // cp.async mapping: 128 threads; thread covers 8 floats of one row per pass
    const int lr = tid >> 2;            // 0..31
    const int lc = (tid & 3) * 8;       // 0,8,16,24

    float acc[4][8][4];
    #pragma unroll
    for (int mf = 0; mf < 4; mf++)
        #pragma unroll
        for (int nf = 0; nf < 8; nf++)
            #pragma unroll
            for (int r = 0; r < 4; r++) acc[mf][nf][r] = 0.0f;

    auto load_stage = [&](int i, int s) {
        const float* Ag = (i < 32) ? xin : hin;
        const float* Bg = (i < 32) ? W : U;
        const int k0 = (i & 31) * BK + lc;
        float* as = smem + s * TILE_FLOATS;
        float* bs = smem + (2 + s) * TILE_FLOATS;
        #pragma unroll
        for (int p = 0; p < 4; p++) {
            int row = lr + p * 32;
            cp_async16(&as[row * SS + lc],     &Ag[(size_t)(bm + row) * KDIM + k0]);
            cp_async16(&as[row * SS + lc + 4], &Ag[(size_t)(bm + row) * KDIM + k0 + 4]);
            cp_async16(&bs[row * SS + lc],     &Bg[(size_t)(bn + row) * KDIM + k0]);
            cp_async16(&bs[row * SS + lc + 4], &Bg[(size_t)(bn + row) * KDIM + k0 + 4]);
        }
        asm volatile("cp.async.commit_group;\n" ::: "memory");
    };

    auto flush = [&](float* dst, int ncols, int coloff) {
        #pragma unroll
        for (int mf = 0; mf < 4; mf++) {
            #pragma unroll
            for (int nf = 0; nf < 8; nf++) {
                int row = bm + wm * 64 + mf * 16 + g;
                int col = coloff + wn * 64 + nf * 8 + 2 * tg;
                *(float2*)&dst[(size_t)row * ncols + col] =
                    make_float2(acc[mf][nf][0], acc[mf][nf][1]);
                *(float2*)&dst[(size_t)(row + 8) * ncols + col] =
                    make_float2(acc[mf][nf][2], acc[mf][nf][3]);
            }
        }
    };

    load_stage(0, 0);
    const int nk = 64;   // 2 x (1024/32)

    for (int i = 0; i < nk; i++) {
        const int s = i & 1;
        if (i + 1 < nk) {
            load_stage(i + 1, s ^ 1);
            asm volatile("cp.async.wait_group 1;\n" ::: "memory");
        } else {
            asm volatile("cp.async.wait_group 0;\n" ::: "memory");
        }
        __syncthreads();

        // float2 views of the current stage
        const float2* as2 = (const float2*)(smem + s * TILE_FLOATS);
        const float2* bs2 = (const float2*)(smem + (2 + s) * TILE_FLOATS);
        const int SP = SS / 2;   // 20 float2 per row

        #pragma unroll
        for (int kk2 = 0; kk2 < BK / 2; kk2 += 4) {     // kk2 = kk/2 in {0,4,8,12}
            uint32_t af[4][4];
            uint32_t bf[8][2];
            // k-pair remap: slot pairs (a0,a2)/(b0,b1) read contiguous cols 2tg,2tg+1.
            // Same map for A and B => dot product unchanged (k-permutation invariant).
            #pragma unroll
            for (int mf = 0; mf < 4; mf++) {
                int r0 = wm * 64 + mf * 16 + g;
                float2 lo = as2[r0 * SP + kk2 + tg];
                float2 hi = as2[(r0 + 8) * SP + kk2 + tg];
                af[mf][0] = __float_as_uint(lo.x);
                af[mf][2] = __float_as_uint(lo.y);
                af[mf][1] = __float_as_uint(hi.x);
                af[mf][3] = __float_as_uint(hi.y);
            }
            #pragma unroll
            for (int nf = 0; nf < 8; nf++) {
                int c0 = wn * 64 + nf * 8 + g;
                float2 b = bs2[c0 * SP + kk2 + tg];
                bf[nf][0] = __float_as_uint(b.x);
                bf[nf][1] = __float_as_uint(b.y);
            }
            #pragma unroll
            for (int mf = 0; mf < 4; mf++)
                #pragma unroll
                for (int nf = 0; nf < 8; nf++) {
                    asm volatile(
                        "mma.sync.aligned.m16n8k8.row.col.f32.tf32.tf32.f32 "
                        "{%0,%1,%2,%3}, {%4,%5,%6,%7}, {%8,%9}, {%0,%1,%2,%3};\n"
                        : "+f"(acc[mf][nf][0]), "+f"(acc[mf][nf][1]),
                          "+f"(acc[mf][nf][2]), "+f"(acc[mf][nf][3])
                        : "r"(af[mf][0]), "r"(af[mf][1]), "r"(af[mf][2]), "r"(af[mf][3]),
                          "r"(bf[nf][0]), "r"(bf[nf][1]));
                }
        }
        __syncthreads();

        // Gate-4 midpoint flush: wx4 complete after first 32 k-tiles
        if (g4 && i == 31) {
            flush(Z, NDIM, bn);
            #pragma unroll
            for (int mf = 0; mf < 4; mf++)
                #pragma unroll
                for (int nf = 0; nf < 8; nf++)
                    #pragma unroll
                    for (int r = 0; r < 4; r++) acc[mf][nf][r] = 0.0f;
        }
    }

    if (g4) flush(U4, HDIM, bn - 4096);   // uh4
    else    flush(Z, NDIM, bn);           // wx + uh
}

__device__ __forceinline__ float sigmoidf_(float z) { return 1.0f / (1.0f + expf(-z)); }

__global__ __launch_bounds__(256)
void xlstm_epilogue_kernel(const float* __restrict__ c_prev,
                           const float* __restrict__ b_all,
                           float* __restrict__ out) {
    int q = blockIdx.x * blockDim.x + threadIdx.x;      // float4 index over [B*H/4)
    if (q >= BDIM * HDIM / 4) return;
    int b  = q >> 8;            // / 256
    int hq = q & 255;           // float4 col
    size_t base4 = (size_t)b * (NDIM / 4) + hq;

    const float4* Z4  = (const float4*)g_Z;
    const float4* U44 = (const float4*)g_U4;
    const float4* bb  = (const float4*)b_all;
    const float4* cp4 = (const float4*)c_prev;
    float4* out4 = (float4*)out;

    float4 z[6];
    #pragma unroll
    for (int k = 0; k < 6; k++) {
        float4 zz = Z4[base4 + (size_t)k * 256];
        float4 bv = bb[k * 256 + hq];
        z[k] = make_float4(zz.x + bv.x, zz.y + bv.y, zz.z + bv.z, zz.w + bv.w);
    }
    float4 u4 = U44[q];
    float4 cp = cp4[q];

    float4 hn, cn;
    {
        float i = sigmoidf_(z[0].x), f = sigmoidf_(z[1].x), o = sigmoidf_(z[2].x);
        float gg = tanhf(z[3].x), m = z[4].x * u4.x, a = sigmoidf_(z[5].x);
        cn.x = f * cp.x + i * gg + a * m;  hn.x = o * tanhf(cn.x);
    }
    {
        float i = sigmoidf_(z[0].y), f = sigmoidf_(z[1].y), o = sigmoidf_(z[2].y);
        float gg = tanhf(z[3].y), m = z[4].y * u4.y, a = sigmoidf_(z[5].y);
        cn.y = f * cp.y + i * gg + a * m;  hn.y = o * tanhf(cn.y);
    }
    {
        float i = sigmoidf_(z[0].z), f = sigmoidf_(z[1].z), o = sigmoidf_(z[2].z);
        float gg = tanhf(z[3].z), m = z[4].z * u4.z, a = sigmoidf_(z[5].z);
        cn.z = f * cp.z + i * gg + a * m;  hn.z = o * tanhf(cn.z);
    }
    {
        float i = sigmoidf_(z[0].w), f = sigmoidf_(z[1].w), o = sigmoidf_(z[2].w);
        float gg = tanhf(z[3].w), m = z[4].w * u4.w, a = sigmoidf_(z[5].w);
        cn.w = f * cp.w + i * gg + a * m;  hn.w = o * tanhf(cn.w);
    }

    out4[q] = hn;
    out4[(size_t)BDIM * HDIM / 4 + q] = cn;
}

extern "C" void kernel_launch(void* const* d_in, const int* in_sizes, int n_in,
                              void* d_out, int out_size) {
    const float* x      = (const float*)d_in[0];
    const float* h_prev = (const float*)d_in[1];
    const float* c_prev = (const float*)d_in[2];
    const float* W_all  = (const float*)d_in[3];
    const float* b_all  = (const float*)d_in[4];
    const float* U_all  = (const float*)d_in[5];
    float* out = (float*)d_out;

    float *pZ = nullptr, *pU4 = nullptr;
    cudaGetSymbolAddress((void**)&pZ, g_Z);
    cudaGetSymbolAddress((void**)&pU4, g_U4);

    const int smem_bytes = 4 * TILE_FLOATS * sizeof(float);   // 81920 B per CTA
    cudaFuncSetAttribute(xlstm_gemm_kernel,
                         cudaFuncAttributeMaxDynamicSharedMemorySize, smem_bytes);

    dim3 grid(NDIM / BN, BDIM / BM);   // 48 x 32
    xlstm_gemm_kernel<<<grid, 128, smem_bytes>>>(x, h_prev, W_all, U_all, pZ, pU4);

    int n4 = BDIM * HDIM / 4;
    xlstm_epilogue_kernel<<<(n4 + 255) / 256, 256>>>(c_prev, b_all, out);
}

// round 5
// speedup vs baseline: 1.1767x; 1.1767x over previous
#include <cuda_runtime.h>
#include <cstdint>
#include <cstddef>

// Problem dims
#define BDIM 4096
#define KDIM 1024
#define HDIM 1024
#define NDIM 6144           // 6 gates * H

// GEMM tiling: CTA 128x128, 8 warps of 64x32, 2 CTAs/SM, 4-stage cp.async pipeline
#define BM 128
#define BN 128
#define BK 16
#define SS 24               // smem row stride in floats (96B, 16B-aligned, LDS.64 conflict-free)
#define SP 12               // row stride in float2
#define TILE_FLOATS (128 * SS)          // 3072
#define STAGE_FLOATS (2 * TILE_FLOATS)  // A + B = 6144 floats = 24576 B
#define NSTAGE 4
#define NK 128              // 2 x (1024/16)

// Scratch: Z[B,6H] (gate-4 slot holds wx4), U4[B,H] holds uh4
__device__ float g_Z[(size_t)BDIM * NDIM];
__device__ float g_U4[(size_t)BDIM * HDIM];

__device__ __forceinline__ void cp_async16(void* smem_ptr, const void* gmem_ptr) {
    uint32_t s = (uint32_t)__cvta_generic_to_shared(smem_ptr);
    asm volatile("cp.async.cg.shared.global [%0], [%1], 16;\n" :: "r"(s), "l"(gmem_ptr));
}

// One fused GEMM: Z = x*W^T + h*U^T (joint K=2048) for all gates; gate-4 tiles
// flush wx4 at the K midpoint and restart accumulation for uh4 -> U4.
__global__ __launch_bounds__(256, 2)
void xlstm_gemm_kernel(const float* __restrict__ xin, const float* __restrict__ hin,
                       const float* __restrict__ W,   const float* __restrict__ U,
                       float* __restrict__ Z, float* __restrict__ U4) {
    extern __shared__ float smem[];
    // layout: stage s at smem + s*STAGE_FLOATS: A[128][SS] then B[128][SS]

    const int tid  = threadIdx.x;
    const int warp = tid >> 5;
    const int lane = tid & 31;
    const int wm = warp & 1;        // 2 warps along M (64 rows each)
    const int wn = warp >> 1;       // 4 warps along N (32 cols each)
    const int g  = lane >> 2;       // 0..7
    const int tg = lane & 3;        // 0..3

    const int bm = blockIdx.y * BM;
    const int bn = blockIdx.x * BN;
    const bool g4 = (blockIdx.x >= 32) && (blockIdx.x < 40);   // cols [4096,5120)

    // cp.async mapping: ci = 16B chunk within row (4 per row), r0 = row group
    const int ci = (tid & 3) * 4;       // float offset 0,4,8,12
    const int r0 = tid >> 2;            // 0..63

    float acc[4][4][4];
    #pragma unroll
    for (int mf = 0; mf < 4; mf++)
        #pragma unroll
        for (int nf = 0; nf < 4; nf++)
            #pragma unroll
            for (int r = 0; r < 4; r++) acc[mf][nf][r] = 0.0f;

    auto load_stage = [&](int i, int s) {
        const float* Ag = (i < 64) ? xin : hin;
        const float* Bg = (i < 64) ? W : U;
        const int k0 = (i & 63) * BK + ci;
        float* as = smem + s * STAGE_FLOATS;
        float* bs = as + TILE_FLOATS;
        #pragma unroll
        for (int p = 0; p < 2; p++) {
            int row = r0 + p * 64;
            cp_async16(&as[row * SS + ci], &Ag[(size_t)(bm + row) * KDIM + k0]);
            cp_async16(&bs[row * SS + ci], &Bg[(size_t)(bn + row) * KDIM + k0]);
        }
        asm volatile("cp.async.commit_group;\n" ::: "memory");
    };

    auto flush = [&](float* dst, int ncols, int coloff) {
        #pragma unroll
        for (int mf = 0; mf < 4; mf++) {
            #pragma unroll
            for (int nf = 0; nf < 4; nf++) {
                int row = bm + wm * 64 + mf * 16 + g;
                int col = coloff + wn * 32 + nf * 8 + 2 * tg;
                *(float2*)&dst[(size_t)row * ncols + col] =
                    make_float2(acc[mf][nf][0], acc[mf][nf][1]);
                *(float2*)&dst[(size_t)(row + 8) * ncols + col] =
                    make_float2(acc[mf][nf][2], acc[mf][nf][3]);
            }
        }
    };

    // Prologue: fill 3 of 4 stages
    load_stage(0, 0);
    load_stage(1, 1);
    load_stage(2, 2);

    #pragma unroll 4
    for (int i = 0; i < NK; i++) {
        // Ensure group i complete (groups i+1, i+2 may remain in flight)
        if (i < NK - 2)       asm volatile("cp.async.wait_group 2;\n" ::: "memory");
        else if (i == NK - 2) asm volatile("cp.async.wait_group 1;\n" ::: "memory");
        else                  asm volatile("cp.async.wait_group 0;\n" ::: "memory");
        __syncthreads();   // all warps: stage i ready AND stage (i-1)%4 fully consumed

        if (i + 3 < NK) load_stage(i + 3, (i + 3) & 3);

        const float2* as2 = (const float2*)(smem + (i & 3) * STAGE_FLOATS);
        const float2* bs2 = as2 + TILE_FLOATS / 2;

        #pragma unroll
        for (int kk2 = 0; kk2 < BK / 2; kk2 += 4) {     // kk2 in {0, 4}
            uint32_t af[4][4];
            uint32_t bf[4][2];
            // k-pair remap: slot pairs (a0,a2)/(b0,b1) read contiguous cols 2tg,2tg+1.
            // Same map for A and B => dot product unchanged (k-permutation invariant).
            #pragma unroll
            for (int mf = 0; mf < 4; mf++) {
                int rr = wm * 64 + mf * 16 + g;
                float2 lo = as2[rr * SP + kk2 + tg];
                float2 hi = as2[(rr + 8) * SP + kk2 + tg];
                af[mf][0] = __float_as_uint(lo.x);
                af[mf][2] = __float_as_uint(lo.y);
                af[mf][1] = __float_as_uint(hi.x);
                af[mf][3] = __float_as_uint(hi.y);
            }
            #pragma unroll
            for (int nf = 0; nf < 4; nf++) {
                int c0 = wn * 32 + nf * 8 + g;
                float2 b = bs2[c0 * SP + kk2 + tg];
                bf[nf][0] = __float_as_uint(b.x);
                bf[nf][1] = __float_as_uint(b.y);
            }
            #pragma unroll
            for (int mf = 0; mf < 4; mf++)
                #pragma unroll
                for (int nf = 0; nf < 4; nf++) {
                    asm volatile(
                        "mma.sync.aligned.m16n8k8.row.col.f32.tf32.tf32.f32 "
                        "{%0,%1,%2,%3}, {%4,%5,%6,%7}, {%8,%9}, {%0,%1,%2,%3};\n"
                        : "+f"(acc[mf][nf][0]), "+f"(acc[mf][nf][1]),
                          "+f"(acc[mf][nf][2]), "+f"(acc[mf][nf][3])
                        : "r"(af[mf][0]), "r"(af[mf][1]), "r"(af[mf][2]), "r"(af[mf][3]),
                          "r"(bf[nf][0]), "r"(bf[nf][1]));
                }
        }

        // Gate-4 midpoint flush: wx4 complete after first 64 k-tiles
        if (g4 && i == 63) {
            flush(Z, NDIM, bn);
            #pragma unroll
            for (int mf = 0; mf < 4; mf++)
                #pragma unroll
                for (int nf = 0; nf < 4; nf++)
                    #pragma unroll
                    for (int r = 0; r < 4; r++) acc[mf][nf][r] = 0.0f;
        }
    }

    if (g4) flush(U4, HDIM, bn - 4096);   // uh4
    else    flush(Z, NDIM, bn);           // wx + uh
}

__device__ __forceinline__ float sigmoidf_(float z) { return 1.0f / (1.0f + expf(-z)); }

__global__ __launch_bounds__(256)
void xlstm_epilogue_kernel(const float* __restrict__ c_prev,
                           const float* __restrict__ b_all,
                           float* __restrict__ out) {
    int q = blockIdx.x * blockDim.x + threadIdx.x;      // float4 index over [B*H/4)
    if (q >= BDIM * HDIM / 4) return;
    int b  = q >> 8;            // / 256
    int hq = q & 255;           // float4 col
    size_t base4 = (size_t)b * (NDIM / 4) + hq;

    const float4* Z4  = (const float4*)g_Z;
    const float4* U44 = (const float4*)g_U4;
    const float4* bb  = (const float4*)b_all;
    const float4* cp4 = (const float4*)c_prev;
    float4* out4 = (float4*)out;

    float4 z[6];
    #pragma unroll
    for (int k = 0; k < 6; k++) {
        float4 zz = Z4[base4 + (size_t)k * 256];
        float4 bv = bb[k * 256 + hq];
        z[k] = make_float4(zz.x + bv.x, zz.y + bv.y, zz.z + bv.z, zz.w + bv.w);
    }
    float4 u4 = U44[q];
    float4 cp = cp4[q];

    float4 hn, cn;
    {
        float i = sigmoidf_(z[0].x), f = sigmoidf_(z[1].x), o = sigmoidf_(z[2].x);
        float gg = tanhf(z[3].x), m = z[4].x * u4.x, a = sigmoidf_(z[5].x);
        cn.x = f * cp.x + i * gg + a * m;  hn.x = o * tanhf(cn.x);
    }
    {
        float i = sigmoidf_(z[0].y), f = sigmoidf_(z[1].y), o = sigmoidf_(z[2].y);
        float gg = tanhf(z[3].y), m = z[4].y * u4.y, a = sigmoidf_(z[5].y);
        cn.y = f * cp.y + i * gg + a * m;  hn.y = o * tanhf(cn.y);
    }
    {
        float i = sigmoidf_(z[0].z), f = sigmoidf_(z[1].z), o = sigmoidf_(z[2].z);
        float gg = tanhf(z[3].z), m = z[4].z * u4.z, a = sigmoidf_(z[5].z);
        cn.z = f * cp.z + i * gg + a * m;  hn.z = o * tanhf(cn.z);
    }
    {
        float i = sigmoidf_(z[0].w), f = sigmoidf_(z[1].w), o = sigmoidf_(z[2].w);
        float gg = tanhf(z[3].w), m = z[4].w * u4.w, a = sigmoidf_(z[5].w);
        cn.w = f * cp.w + i * gg + a * m;  hn.w = o * tanhf(cn.w);
    }

    out4[q] = hn;
    out4[(size_t)BDIM * HDIM / 4 + q] = cn;
}

extern "C" void kernel_launch(void* const* d_in, const int* in_sizes, int n_in,
                              void* d_out, int out_size) {
    const float* x      = (const float*)d_in[0];
    const float* h_prev = (const float*)d_in[1];
    const float* c_prev = (const float*)d_in[2];
    const float* W_all  = (const float*)d_in[3];
    const float* b_all  = (const float*)d_in[4];
    const float* U_all  = (const float*)d_in[5];
    float* out = (float*)d_out;

    float *pZ = nullptr, *pU4 = nullptr;
    cudaGetSymbolAddress((void**)&pZ, g_Z);
    cudaGetSymbolAddress((void**)&pU4, g_U4);

    const int smem_bytes = NSTAGE * STAGE_FLOATS * sizeof(float);   // 98304 B per CTA
    cudaFuncSetAttribute(xlstm_gemm_kernel,
                         cudaFuncAttributeMaxDynamicSharedMemorySize, smem_bytes);

    dim3 grid(NDIM / BN, BDIM / BM);   // 48 x 32
    xlstm_gemm_kernel<<<grid, 256, smem_bytes>>>(x, h_prev, W_all, U_all, pZ, pU4);

    int n4 = BDIM * HDIM / 4;
    xlstm_epilogue_kernel<<<(n4 + 255) / 256, 256>>>(c_prev, b_all, out);
}